// round 2
// baseline (speedup 1.0000x reference)
#include <cuda_runtime.h>

// Problem constants
#define SLEN 4096
#define DIM  512
#define NBATCH 4                 // 2B
#define ROWS (NBATCH * SLEN)     // 16384

// ---------------- device scratch (no allocs allowed) ----------------
__device__ float g_norms[(size_t)ROWS * DIM];
__device__ float g_Q[(size_t)ROWS * DIM];
__device__ float g_Kt[(size_t)ROWS * DIM];
__device__ float g_Vt[(size_t)ROWS * DIM];
__device__ float g_Sc[(size_t)NBATCH * SLEN * SLEN];   // 256 MiB scores
__device__ float g_X[(size_t)ROWS * DIM];
__device__ float g_O[(size_t)ROWS * DIM];

// ---------------- reduction helpers ----------------
__device__ __forceinline__ float warp_sum(float v) {
    #pragma unroll
    for (int o = 16; o > 0; o >>= 1) v += __shfl_xor_sync(0xFFFFFFFFu, v, o);
    return v;
}
__device__ __forceinline__ float warp_max(float v) {
    #pragma unroll
    for (int o = 16; o > 0; o >>= 1) v = fmaxf(v, __shfl_xor_sync(0xFFFFFFFFu, v, o));
    return v;
}

// ---------------- input LayerNorm: rows 0..8191 text(ln_t), 8192..16383 img(ln_i) ----
__global__ void ln_in_kernel(const float* __restrict__ text, const float* __restrict__ img,
                             const float* __restrict__ gt, const float* __restrict__ bt,
                             const float* __restrict__ gi, const float* __restrict__ bi,
                             float* __restrict__ out)
{
    int row = blockIdx.x;
    const float* src; const float* g; const float* b;
    if (row < 2 * SLEN) { src = text + (size_t)row * DIM;            g = gt; b = bt; }
    else                { src = img  + (size_t)(row - 2*SLEN) * DIM; g = gi; b = bi; }

    int t = threadIdx.x;                 // 128 threads, float4 each
    float4 v = ((const float4*)src)[t];
    float s  = v.x + v.y + v.z + v.w;
    float ss = v.x*v.x + v.y*v.y + v.z*v.z + v.w*v.w;

    __shared__ float red[8];
    s = warp_sum(s); ss = warp_sum(ss);
    int w = t >> 5, l = t & 31;
    if (l == 0) { red[w] = s; red[4 + w] = ss; }
    __syncthreads();
    float st = red[0] + red[1] + red[2] + red[3];
    float sst = red[4] + red[5] + red[6] + red[7];

    float mu  = st * (1.0f / DIM);
    float var = sst * (1.0f / DIM) - mu * mu;
    float r   = rsqrtf(var + 1e-5f);

    float4 gv = ((const float4*)g)[t];
    float4 bv = ((const float4*)b)[t];
    float4 o;
    o.x = (v.x - mu) * r * gv.x + bv.x;
    o.y = (v.y - mu) * r * gv.y + bv.y;
    o.z = (v.z - mu) * r * gv.z + bv.z;
    o.w = (v.w - mu) * r * gv.w + bv.w;
    ((float4*)(out + (size_t)row * DIM))[t] = o;
}

// ---------------- GEMM NT: C[m,n] = alpha * sum_k A[m,k]*B[n,k] (+bias[n]) ----------
// Tiles: BM=BN=128, BK=8, 256 threads, 8x8 per thread. All dims multiples of tiles.
__global__ void __launch_bounds__(256) gemm_nt_kernel(
    const float* __restrict__ A, const float* __restrict__ B,
    const float* __restrict__ bias, float* __restrict__ C,
    int N, int K, float alpha,
    size_t strA, size_t strB, size_t strC)
{
    __shared__ float As[8][132];
    __shared__ float Bs[8][132];

    const float* Ab = A + blockIdx.z * strA + (size_t)blockIdx.y * 128 * K;
    const float* Bb = B + blockIdx.z * strB + (size_t)blockIdx.x * 128 * K;
    float*       Cb = C + blockIdx.z * strC + (size_t)blockIdx.y * 128 * N + (size_t)blockIdx.x * 128;

    int tid = threadIdx.x;
    int tx = tid & 15, ty = tid >> 4;
    int lm = tid >> 1;           // 0..127
    int lk = (tid & 1) * 4;      // 0 or 4

    float acc[8][8];
    #pragma unroll
    for (int i = 0; i < 8; i++)
        #pragma unroll
        for (int j = 0; j < 8; j++) acc[i][j] = 0.0f;

    for (int k0 = 0; k0 < K; k0 += 8) {
        float4 av = *(const float4*)(Ab + (size_t)lm * K + k0 + lk);
        float4 bv = *(const float4*)(Bb + (size_t)lm * K + k0 + lk);
        __syncthreads();
        As[lk + 0][lm] = av.x; As[lk + 1][lm] = av.y; As[lk + 2][lm] = av.z; As[lk + 3][lm] = av.w;
        Bs[lk + 0][lm] = bv.x; Bs[lk + 1][lm] = bv.y; Bs[lk + 2][lm] = bv.z; Bs[lk + 3][lm] = bv.w;
        __syncthreads();
        #pragma unroll
        for (int k = 0; k < 8; k++) {
            float a[8], b[8];
            #pragma unroll
            for (int i = 0; i < 8; i++) a[i] = As[k][ty * 8 + i];
            #pragma unroll
            for (int j = 0; j < 8; j++) b[j] = Bs[k][tx * 8 + j];
            #pragma unroll
            for (int i = 0; i < 8; i++)
                #pragma unroll
                for (int j = 0; j < 8; j++)
                    acc[i][j] = fmaf(a[i], b[j], acc[i][j]);
        }
    }

    int cbase = blockIdx.x * 128;
    #pragma unroll
    for (int i = 0; i < 8; i++) {
        int m = ty * 8 + i;
        #pragma unroll
        for (int j = 0; j < 8; j++) {
            int n = tx * 8 + j;
            float v = acc[i][j] * alpha;
            if (bias) v += bias[cbase + n];
            Cb[(size_t)m * N + n] = v;
        }
    }
}

// ---------------- GEMM NN: C[m,n] = sum_k A[m,k]*B[k,n] (attn @ V) --------------
__global__ void __launch_bounds__(256) gemm_nn_kernel(
    const float* __restrict__ A, const float* __restrict__ B,
    float* __restrict__ C,
    int N, int K,
    size_t strA, size_t strB, size_t strC)
{
    __shared__ float As[8][132];
    __shared__ float Bs[8][132];

    const float* Ab = A + blockIdx.z * strA + (size_t)blockIdx.y * 128 * K;
    const float* Bb = B + blockIdx.z * strB + (size_t)blockIdx.x * 128;
    float*       Cb = C + blockIdx.z * strC + (size_t)blockIdx.y * 128 * N + (size_t)blockIdx.x * 128;

    int tid = threadIdx.x;
    int tx = tid & 15, ty = tid >> 4;
    int lm  = tid >> 1;          // A loader: row 0..127
    int lk  = (tid & 1) * 4;     // A loader: k 0 or 4
    int lkb = tid >> 5;          // B loader: k-row 0..7
    int lnb = (tid & 31) * 4;    // B loader: n 0..124

    float acc[8][8];
    #pragma unroll
    for (int i = 0; i < 8; i++)
        #pragma unroll
        for (int j = 0; j < 8; j++) acc[i][j] = 0.0f;

    for (int k0 = 0; k0 < K; k0 += 8) {
        float4 av = *(const float4*)(Ab + (size_t)lm * K + k0 + lk);
        float4 bv = *(const float4*)(Bb + (size_t)(k0 + lkb) * N + lnb);
        __syncthreads();
        As[lk + 0][lm] = av.x; As[lk + 1][lm] = av.y; As[lk + 2][lm] = av.z; As[lk + 3][lm] = av.w;
        *(float4*)&Bs[lkb][lnb] = bv;
        __syncthreads();
        #pragma unroll
        for (int k = 0; k < 8; k++) {
            float a[8], b[8];
            #pragma unroll
            for (int i = 0; i < 8; i++) a[i] = As[k][ty * 8 + i];
            #pragma unroll
            for (int j = 0; j < 8; j++) b[j] = Bs[k][tx * 8 + j];
            #pragma unroll
            for (int i = 0; i < 8; i++)
                #pragma unroll
                for (int j = 0; j < 8; j++)
                    acc[i][j] = fmaf(a[i], b[j], acc[i][j]);
        }
    }

    #pragma unroll
    for (int i = 0; i < 8; i++) {
        int m = ty * 8 + i;
        #pragma unroll
        for (int j = 0; j < 8; j++) {
            int n = tx * 8 + j;
            Cb[(size_t)m * N + n] = acc[i][j];
        }
    }
}

// ---------------- row softmax over 4096, fully register-resident ----------------
__global__ void softmax_kernel(float* __restrict__ Sc)
{
    size_t row = blockIdx.x;
    float4* p = (float4*)(Sc + row * (size_t)SLEN);
    int t = threadIdx.x;                 // 256 threads x 4 float4 = 4096 floats

    float4 v[4];
    #pragma unroll
    for (int i = 0; i < 4; i++) v[i] = p[t + i * 256];

    float m = -1e30f;
    #pragma unroll
    for (int i = 0; i < 4; i++) {
        m = fmaxf(m, fmaxf(fmaxf(v[i].x, v[i].y), fmaxf(v[i].z, v[i].w)));
    }
    __shared__ float red[8];
    m = warp_max(m);
    int w = t >> 5, l = t & 31;
    if (l == 0) red[w] = m;
    __syncthreads();
    float bm = red[0];
    #pragma unroll
    for (int i = 1; i < 8; i++) bm = fmaxf(bm, red[i]);

    float sum = 0.0f;
    #pragma unroll
    for (int i = 0; i < 4; i++) {
        v[i].x = __expf(v[i].x - bm); v[i].y = __expf(v[i].y - bm);
        v[i].z = __expf(v[i].z - bm); v[i].w = __expf(v[i].w - bm);
        sum += v[i].x + v[i].y + v[i].z + v[i].w;
    }
    sum = warp_sum(sum);
    __syncthreads();                     // red reuse
    if (l == 0) red[w] = sum;
    __syncthreads();
    float bs = red[0] + red[1] + red[2] + red[3] + red[4] + red[5] + red[6] + red[7];
    float inv = 1.0f / bs;

    #pragma unroll
    for (int i = 0; i < 4; i++) {
        v[i].x *= inv; v[i].y *= inv; v[i].z *= inv; v[i].w *= inv;
        p[t + i * 256] = v[i];
    }
}

// ---------------- output LayerNorm: one read of x, both LN variants written ------
__global__ void ln_out_kernel(const float* __restrict__ X,
                              const float* __restrict__ gt, const float* __restrict__ bt,
                              const float* __restrict__ gi, const float* __restrict__ bi,
                              float* __restrict__ out)
{
    int row = blockIdx.x;                // 0..16383
    int t = threadIdx.x;                 // 128 threads
    float4 v = ((const float4*)(X + (size_t)row * DIM))[t];
    float s  = v.x + v.y + v.z + v.w;
    float ss = v.x*v.x + v.y*v.y + v.z*v.z + v.w*v.w;

    __shared__ float red[8];
    s = warp_sum(s); ss = warp_sum(ss);
    int w = t >> 5, l = t & 31;
    if (l == 0) { red[w] = s; red[4 + w] = ss; }
    __syncthreads();
    float st  = red[0] + red[1] + red[2] + red[3];
    float sst = red[4] + red[5] + red[6] + red[7];

    float mu  = st * (1.0f / DIM);
    float var = sst * (1.0f / DIM) - mu * mu;
    float r   = rsqrtf(var + 1e-5f);
    float nx = (v.x - mu) * r, ny = (v.y - mu) * r, nz = (v.z - mu) * r, nw = (v.w - mu) * r;

    float4 g1 = ((const float4*)gt)[t]; float4 b1 = ((const float4*)bt)[t];
    float4 o1; o1.x = nx * g1.x + b1.x; o1.y = ny * g1.y + b1.y;
               o1.z = nz * g1.z + b1.z; o1.w = nw * g1.w + b1.w;
    ((float4*)(out + (size_t)row * DIM))[t] = o1;

    float4 g2 = ((const float4*)gi)[t]; float4 b2 = ((const float4*)bi)[t];
    float4 o2; o2.x = nx * g2.x + b2.x; o2.y = ny * g2.y + b2.y;
               o2.z = nz * g2.z + b2.z; o2.w = nw * g2.w + b2.w;
    ((float4*)(out + (size_t)(ROWS + row) * DIM))[t] = o2;
}

// ---------------- launch ----------------
extern "C" void kernel_launch(void* const* d_in, const int* in_sizes, int n_in,
                              void* d_out, int out_size)
{
    const float* text   = (const float*)d_in[0];
    const float* img    = (const float*)d_in[1];
    const float* ln_t_g = (const float*)d_in[2];
    const float* ln_t_b = (const float*)d_in[3];
    const float* ln_i_g = (const float*)d_in[4];
    const float* ln_i_b = (const float*)d_in[5];
    const float* Wq  = (const float*)d_in[6];  const float* bq  = (const float*)d_in[7];
    const float* Wkt = (const float*)d_in[8];  const float* bkt = (const float*)d_in[9];
    const float* Wvt = (const float*)d_in[10]; const float* bvt = (const float*)d_in[11];
    const float* Wki = (const float*)d_in[12]; const float* bki = (const float*)d_in[13];
    const float* Wvi = (const float*)d_in[14]; const float* bvi = (const float*)d_in[15];
    const float* Wo  = (const float*)d_in[16]; const float* bo  = (const float*)d_in[17];
    float* out = (float*)d_out;

    float *gn, *gq, *gk, *gv, *gs, *gx, *go;
    cudaGetSymbolAddress((void**)&gn, g_norms);
    cudaGetSymbolAddress((void**)&gq, g_Q);
    cudaGetSymbolAddress((void**)&gk, g_Kt);
    cudaGetSymbolAddress((void**)&gv, g_Vt);
    cudaGetSymbolAddress((void**)&gs, g_Sc);
    cudaGetSymbolAddress((void**)&gx, g_X);
    cudaGetSymbolAddress((void**)&go, g_O);

    const size_t half = (size_t)2 * SLEN * DIM;   // 8192 rows
    const float scale = 0.044194173824159216f;    // 512^-0.5

    // 1) input LN -> g_norms
    ln_in_kernel<<<ROWS, 128>>>(text, img, ln_t_g, ln_t_b, ln_i_g, ln_i_b, gn);

    // 2) projections (NT): N=512, K=512
    dim3 gFull(DIM / 128, ROWS / 128);     // (4,128)
    dim3 gHalf(DIM / 128, (ROWS/2) / 128); // (4,64)
    gemm_nt_kernel<<<gFull, 256>>>(gn, Wq, bq, gq, DIM, DIM, 1.0f, 0, 0, 0);
    gemm_nt_kernel<<<gHalf, 256>>>(gn,        Wkt, bkt, gk,        DIM, DIM, 1.0f, 0, 0, 0);
    gemm_nt_kernel<<<gHalf, 256>>>(gn + half, Wki, bki, gk + half, DIM, DIM, 1.0f, 0, 0, 0);
    gemm_nt_kernel<<<gHalf, 256>>>(gn,        Wvt, bvt, gv,        DIM, DIM, 1.0f, 0, 0, 0);
    gemm_nt_kernel<<<gHalf, 256>>>(gn + half, Wvi, bvi, gv + half, DIM, DIM, 1.0f, 0, 0, 0);

    // 3) scores = scale * Q @ K^T  (batched NT): N=4096, K=512
    dim3 gScores(SLEN / 128, SLEN / 128, NBATCH);  // (32,32,4)
    gemm_nt_kernel<<<gScores, 256>>>(gq, gk, nullptr, gs, SLEN, DIM, scale,
                                     (size_t)SLEN * DIM, (size_t)SLEN * DIM,
                                     (size_t)SLEN * SLEN);

    // 4) softmax rows
    softmax_kernel<<<ROWS, 256>>>(gs);

    // 5) x = attn @ V (batched NN): N=512, K=4096
    dim3 gPV(DIM / 128, SLEN / 128, NBATCH);       // (4,32,4)
    gemm_nn_kernel<<<gPV, 256>>>(gs, gv, gx, DIM, SLEN,
                                 (size_t)SLEN * SLEN, (size_t)SLEN * DIM,
                                 (size_t)SLEN * DIM);

    // 6) out-proj (NT)
    gemm_nt_kernel<<<gFull, 256>>>(gx, Wo, bo, go, DIM, DIM, 1.0f, 0, 0, 0);

    // 7) final double LayerNorm -> both output halves
    ln_out_kernel<<<ROWS, 128>>>(go, ln_t_g, ln_t_b, ln_i_g, ln_i_b, out);
}

// round 7
// speedup vs baseline: 1.0530x; 1.0530x over previous
#include <cuda_runtime.h>

// Problem constants
#define SLEN 4096
#define DIM  512
#define NBATCH 4                 // 2B
#define ROWS (NBATCH * SLEN)     // 16384

// ---------------- device scratch (no allocs allowed) ----------------
__device__ float g_norms[(size_t)ROWS * DIM];
__device__ float g_Q[(size_t)ROWS * DIM];
__device__ float g_Kt[(size_t)ROWS * DIM];
__device__ float g_Vt[(size_t)ROWS * DIM];
__device__ float g_Sc[(size_t)NBATCH * SLEN * SLEN];   // 256 MiB scores
__device__ float g_X[(size_t)ROWS * DIM];
__device__ float g_O[(size_t)ROWS * DIM];

// ---------------- reduction helpers ----------------
__device__ __forceinline__ float warp_sum(float v) {
    #pragma unroll
    for (int o = 16; o > 0; o >>= 1) v += __shfl_xor_sync(0xFFFFFFFFu, v, o);
    return v;
}
__device__ __forceinline__ float warp_max(float v) {
    #pragma unroll
    for (int o = 16; o > 0; o >>= 1) v = fmaxf(v, __shfl_xor_sync(0xFFFFFFFFu, v, o));
    return v;
}

// ---------------- input LayerNorm: rows 0..8191 text(ln_t), 8192..16383 img(ln_i) ----
__global__ void ln_in_kernel(const float* __restrict__ text, const float* __restrict__ img,
                             const float* __restrict__ gt, const float* __restrict__ bt,
                             const float* __restrict__ gi, const float* __restrict__ bi,
                             float* __restrict__ out)
{
    int row = blockIdx.x;
    const float* src; const float* g; const float* b;
    if (row < 2 * SLEN) { src = text + (size_t)row * DIM;            g = gt; b = bt; }
    else                { src = img  + (size_t)(row - 2*SLEN) * DIM; g = gi; b = bi; }

    int t = threadIdx.x;                 // 128 threads, float4 each
    float4 v = ((const float4*)src)[t];
    float s  = v.x + v.y + v.z + v.w;
    float ss = v.x*v.x + v.y*v.y + v.z*v.z + v.w*v.w;

    __shared__ float red[8];
    s = warp_sum(s); ss = warp_sum(ss);
    int w = t >> 5, l = t & 31;
    if (l == 0) { red[w] = s; red[4 + w] = ss; }
    __syncthreads();
    float st = red[0] + red[1] + red[2] + red[3];
    float sst = red[4] + red[5] + red[6] + red[7];

    float mu  = st * (1.0f / DIM);
    float var = sst * (1.0f / DIM) - mu * mu;
    float r   = rsqrtf(var + 1e-5f);

    float4 gv = ((const float4*)g)[t];
    float4 bv = ((const float4*)b)[t];
    float4 o;
    o.x = (v.x - mu) * r * gv.x + bv.x;
    o.y = (v.y - mu) * r * gv.y + bv.y;
    o.z = (v.z - mu) * r * gv.z + bv.z;
    o.w = (v.w - mu) * r * gv.w + bv.w;
    ((float4*)(out + (size_t)row * DIM))[t] = o;
}

// ---------------- GEMM NT: C[m,n] = alpha * sum_k A[m,k]*B[n,k] (+bias[n]) ----------
// Tiles: BM=BN=128, BK=8, 256 threads, 8x8 per thread. All dims multiples of tiles.
__global__ void __launch_bounds__(256) gemm_nt_kernel(
    const float* __restrict__ A, const float* __restrict__ B,
    const float* __restrict__ bias, float* __restrict__ C,
    int N, int K, float alpha,
    size_t strA, size_t strB, size_t strC)
{
    __shared__ float As[8][132];
    __shared__ float Bs[8][132];

    const float* Ab = A + blockIdx.z * strA + (size_t)blockIdx.y * 128 * K;
    const float* Bb = B + blockIdx.z * strB + (size_t)blockIdx.x * 128 * K;
    float*       Cb = C + blockIdx.z * strC + (size_t)blockIdx.y * 128 * N + (size_t)blockIdx.x * 128;

    int tid = threadIdx.x;
    int tx = tid & 15, ty = tid >> 4;
    int lm = tid >> 1;           // 0..127
    int lk = (tid & 1) * 4;      // 0 or 4

    float acc[8][8];
    #pragma unroll
    for (int i = 0; i < 8; i++)
        #pragma unroll
        for (int j = 0; j < 8; j++) acc[i][j] = 0.0f;

    for (int k0 = 0; k0 < K; k0 += 8) {
        float4 av = *(const float4*)(Ab + (size_t)lm * K + k0 + lk);
        float4 bv = *(const float4*)(Bb + (size_t)lm * K + k0 + lk);
        __syncthreads();
        As[lk + 0][lm] = av.x; As[lk + 1][lm] = av.y; As[lk + 2][lm] = av.z; As[lk + 3][lm] = av.w;
        Bs[lk + 0][lm] = bv.x; Bs[lk + 1][lm] = bv.y; Bs[lk + 2][lm] = bv.z; Bs[lk + 3][lm] = bv.w;
        __syncthreads();
        #pragma unroll
        for (int k = 0; k < 8; k++) {
            float a[8], b[8];
            #pragma unroll
            for (int i = 0; i < 8; i++) a[i] = As[k][ty * 8 + i];
            #pragma unroll
            for (int j = 0; j < 8; j++) b[j] = Bs[k][tx * 8 + j];
            #pragma unroll
            for (int i = 0; i < 8; i++)
                #pragma unroll
                for (int j = 0; j < 8; j++)
                    acc[i][j] = fmaf(a[i], b[j], acc[i][j]);
        }
    }

    int cbase = blockIdx.x * 128;
    #pragma unroll
    for (int i = 0; i < 8; i++) {
        int m = ty * 8 + i;
        #pragma unroll
        for (int j = 0; j < 8; j++) {
            int n = tx * 8 + j;
            float v = acc[i][j] * alpha;
            if (bias) v += bias[cbase + n];
            Cb[(size_t)m * N + n] = v;
        }
    }
}

// ---------------- GEMM NN: C[m,n] = sum_k A[m,k]*B[k,n] (attn @ V) --------------
__global__ void __launch_bounds__(256) gemm_nn_kernel(
    const float* __restrict__ A, const float* __restrict__ B,
    float* __restrict__ C,
    int N, int K,
    size_t strA, size_t strB, size_t strC)
{
    __shared__ float As[8][132];
    __shared__ float Bs[8][132];

    const float* Ab = A + blockIdx.z * strA + (size_t)blockIdx.y * 128 * K;
    const float* Bb = B + blockIdx.z * strB + (size_t)blockIdx.x * 128;
    float*       Cb = C + blockIdx.z * strC + (size_t)blockIdx.y * 128 * N + (size_t)blockIdx.x * 128;

    int tid = threadIdx.x;
    int tx = tid & 15, ty = tid >> 4;
    int lm  = tid >> 1;          // A loader: row 0..127
    int lk  = (tid & 1) * 4;     // A loader: k 0 or 4
    int lkb = tid >> 5;          // B loader: k-row 0..7
    int lnb = (tid & 31) * 4;    // B loader: n 0..124

    float acc[8][8];
    #pragma unroll
    for (int i = 0; i < 8; i++)
        #pragma unroll
        for (int j = 0; j < 8; j++) acc[i][j] = 0.0f;

    for (int k0 = 0; k0 < K; k0 += 8) {
        float4 av = *(const float4*)(Ab + (size_t)lm * K + k0 + lk);
        float4 bv = *(const float4*)(Bb + (size_t)(k0 + lkb) * N + lnb);
        __syncthreads();
        As[lk + 0][lm] = av.x; As[lk + 1][lm] = av.y; As[lk + 2][lm] = av.z; As[lk + 3][lm] = av.w;
        *(float4*)&Bs[lkb][lnb] = bv;
        __syncthreads();
        #pragma unroll
        for (int k = 0; k < 8; k++) {
            float a[8], b[8];
            #pragma unroll
            for (int i = 0; i < 8; i++) a[i] = As[k][ty * 8 + i];
            #pragma unroll
            for (int j = 0; j < 8; j++) b[j] = Bs[k][tx * 8 + j];
            #pragma unroll
            for (int i = 0; i < 8; i++)
                #pragma unroll
                for (int j = 0; j < 8; j++)
                    acc[i][j] = fmaf(a[i], b[j], acc[i][j]);
        }
    }

    #pragma unroll
    for (int i = 0; i < 8; i++) {
        int m = ty * 8 + i;
        #pragma unroll
        for (int j = 0; j < 8; j++) {
            int n = tx * 8 + j;
            Cb[(size_t)m * N + n] = acc[i][j];
        }
    }
}

// ---------------- row softmax over 4096, fully register-resident ----------------
__global__ void softmax_kernel(float* __restrict__ Sc)
{
    size_t row = blockIdx.x;
    float4* p = (float4*)(Sc + row * (size_t)SLEN);
    int t = threadIdx.x;                 // 256 threads x 4 float4 = 4096 floats

    float4 v[4];
    #pragma unroll
    for (int i = 0; i < 4; i++) v[i] = p[t + i * 256];

    float m = -1e30f;
    #pragma unroll
    for (int i = 0; i < 4; i++) {
        m = fmaxf(m, fmaxf(fmaxf(v[i].x, v[i].y), fmaxf(v[i].z, v[i].w)));
    }
    __shared__ float red[8];
    m = warp_max(m);
    int w = t >> 5, l = t & 31;
    if (l == 0) red[w] = m;
    __syncthreads();
    float bm = red[0];
    #pragma unroll
    for (int i = 1; i < 8; i++) bm = fmaxf(bm, red[i]);

    float sum = 0.0f;
    #pragma unroll
    for (int i = 0; i < 4; i++) {
        v[i].x = __expf(v[i].x - bm); v[i].y = __expf(v[i].y - bm);
        v[i].z = __expf(v[i].z - bm); v[i].w = __expf(v[i].w - bm);
        sum += v[i].x + v[i].y + v[i].z + v[i].w;
    }
    sum = warp_sum(sum);
    __syncthreads();                     // red reuse
    if (l == 0) red[w] = sum;
    __syncthreads();
    float bs = red[0] + red[1] + red[2] + red[3] + red[4] + red[5] + red[6] + red[7];
    float inv = 1.0f / bs;

    #pragma unroll
    for (int i = 0; i < 4; i++) {
        v[i].x *= inv; v[i].y *= inv; v[i].z *= inv; v[i].w *= inv;
        p[t + i * 256] = v[i];
    }
}

// ---------------- output LayerNorm: one read of x, both LN variants written ------
__global__ void ln_out_kernel(const float* __restrict__ X,
                              const float* __restrict__ gt, const float* __restrict__ bt,
                              const float* __restrict__ gi, const float* __restrict__ bi,
                              float* __restrict__ out)
{
    int row = blockIdx.x;                // 0..16383
    int t = threadIdx.x;                 // 128 threads
    float4 v = ((const float4*)(X + (size_t)row * DIM))[t];
    float s  = v.x + v.y + v.z + v.w;
    float ss = v.x*v.x + v.y*v.y + v.z*v.z + v.w*v.w;

    __shared__ float red[8];
    s = warp_sum(s); ss = warp_sum(ss);
    int w = t >> 5, l = t & 31;
    if (l == 0) { red[w] = s; red[4 + w] = ss; }
    __syncthreads();
    float st  = red[0] + red[1] + red[2] + red[3];
    float sst = red[4] + red[5] + red[6] + red[7];

    float mu  = st * (1.0f / DIM);
    float var = sst * (1.0f / DIM) - mu * mu;
    float r   = rsqrtf(var + 1e-5f);
    float nx = (v.x - mu) * r, ny = (v.y - mu) * r, nz = (v.z - mu) * r, nw = (v.w - mu) * r;

    float4 g1 = ((const float4*)gt)[t]; float4 b1 = ((const float4*)bt)[t];
    float4 o1; o1.x = nx * g1.x + b1.x; o1.y = ny * g1.y + b1.y;
               o1.z = nz * g1.z + b1.z; o1.w = nw * g1.w + b1.w;
    ((float4*)(out + (size_t)row * DIM))[t] = o1;

    float4 g2 = ((const float4*)gi)[t]; float4 b2 = ((const float4*)bi)[t];
    float4 o2; o2.x = nx * g2.x + b2.x; o2.y = ny * g2.y + b2.y;
               o2.z = nz * g2.z + b2.z; o2.w = nw * g2.w + b2.w;
    ((float4*)(out + (size_t)(ROWS + row) * DIM))[t] = o2;
}

// ---------------- launch ----------------
extern "C" void kernel_launch(void* const* d_in, const int* in_sizes, int n_in,
                              void* d_out, int out_size)
{
    const float* text   = (const float*)d_in[0];
    const float* img    = (const float*)d_in[1];
    const float* ln_t_g = (const float*)d_in[2];
    const float* ln_t_b = (const float*)d_in[3];
    const float* ln_i_g = (const float*)d_in[4];
    const float* ln_i_b = (const float*)d_in[5];
    const float* Wq  = (const float*)d_in[6];  const float* bq  = (const float*)d_in[7];
    const float* Wkt = (const float*)d_in[8];  const float* bkt = (const float*)d_in[9];
    const float* Wvt = (const float*)d_in[10]; const float* bvt = (const float*)d_in[11];
    const float* Wki = (const float*)d_in[12]; const float* bki = (const float*)d_in[13];
    const float* Wvi = (const float*)d_in[14]; const float* bvi = (const float*)d_in[15];
    const float* Wo  = (const float*)d_in[16]; const float* bo  = (const float*)d_in[17];
    float* out = (float*)d_out;

    float *gn, *gq, *gk, *gv, *gs, *gx, *go;
    cudaGetSymbolAddress((void**)&gn, g_norms);
    cudaGetSymbolAddress((void**)&gq, g_Q);
    cudaGetSymbolAddress((void**)&gk, g_Kt);
    cudaGetSymbolAddress((void**)&gv, g_Vt);
    cudaGetSymbolAddress((void**)&gs, g_Sc);
    cudaGetSymbolAddress((void**)&gx, g_X);
    cudaGetSymbolAddress((void**)&go, g_O);

    const size_t half = (size_t)2 * SLEN * DIM;   // 8192 rows
    const float scale = 0.044194173824159216f;    // 512^-0.5

    // 1) input LN -> g_norms
    ln_in_kernel<<<ROWS, 128>>>(text, img, ln_t_g, ln_t_b, ln_i_g, ln_i_b, gn);

    // 2) projections (NT): N=512, K=512
    dim3 gFull(DIM / 128, ROWS / 128);     // (4,128)
    dim3 gHalf(DIM / 128, (ROWS/2) / 128); // (4,64)
    gemm_nt_kernel<<<gFull, 256>>>(gn, Wq, bq, gq, DIM, DIM, 1.0f, 0, 0, 0);
    gemm_nt_kernel<<<gHalf, 256>>>(gn,        Wkt, bkt, gk,        DIM, DIM, 1.0f, 0, 0, 0);
    gemm_nt_kernel<<<gHalf, 256>>>(gn + half, Wki, bki, gk + half, DIM, DIM, 1.0f, 0, 0, 0);
    gemm_nt_kernel<<<gHalf, 256>>>(gn,        Wvt, bvt, gv,        DIM, DIM, 1.0f, 0, 0, 0);
    gemm_nt_kernel<<<gHalf, 256>>>(gn + half, Wvi, bvi, gv + half, DIM, DIM, 1.0f, 0, 0, 0);

    // 3) scores = scale * Q @ K^T  (batched NT): N=4096, K=512
    dim3 gScores(SLEN / 128, SLEN / 128, NBATCH);  // (32,32,4)
    gemm_nt_kernel<<<gScores, 256>>>(gq, gk, nullptr, gs, SLEN, DIM, scale,
                                     (size_t)SLEN * DIM, (size_t)SLEN * DIM,
                                     (size_t)SLEN * SLEN);

    // 4) softmax rows
    softmax_kernel<<<ROWS, 256>>>(gs);

    // 5) x = attn @ V (batched NN): N=512, K=4096
    dim3 gPV(DIM / 128, SLEN / 128, NBATCH);       // (4,32,4)
    gemm_nn_kernel<<<gPV, 256>>>(gs, gv, gx, DIM, SLEN,
                                 (size_t)SLEN * SLEN, (size_t)SLEN * DIM,
                                 (size_t)SLEN * DIM);

    // 6) out-proj (NT)
    gemm_nt_kernel<<<gFull, 256>>>(gx, Wo, bo, go, DIM, DIM, 1.0f, 0, 0, 0);

    // 7) final double LayerNorm -> both output halves
    ln_out_kernel<<<ROWS, 128>>>(go, ln_t_g, ln_t_b, ln_i_g, ln_i_b, out);
}

// round 11
// speedup vs baseline: 2.5642x; 2.4351x over previous
#include <cuda_runtime.h>
#include <cuda_bf16.h>
#include <cstdint>

#define SLEN 4096
#define DIM  512
#define NB   4
#define ROWS (NB*SLEN)          // 16384
#define K3   (3*DIM)            // 1536
#define KP3  (3*SLEN)           // 12288

// ---------------- device scratch ----------------
__device__ __align__(128) __nv_bfloat16 g_nA[(size_t)ROWS*K3];
__device__ __align__(128) __nv_bfloat16 g_nB[(size_t)ROWS*K3];
__device__ __align__(128) __nv_bfloat16 g_W2[6][(size_t)DIM*K3];
__device__ __align__(128) float         g_Qf[(size_t)ROWS*DIM];
__device__ __align__(128) __nv_bfloat16 g_Q2[(size_t)ROWS*K3];
__device__ __align__(128) float         g_Kf[(size_t)ROWS*DIM];
__device__ __align__(128) __nv_bfloat16 g_K2[(size_t)ROWS*K3];
__device__ __align__(128) float         g_Vtf[(size_t)DIM*ROWS];
__device__ __align__(128) __nv_bfloat16 g_Vt2[(size_t)NB*DIM*KP3];
__device__ __align__(128) float         g_Sc[(size_t)NB*SLEN*SLEN];
__device__ __align__(128) __nv_bfloat16 g_P2[(size_t)ROWS*KP3];
__device__ __align__(128) float         g_Xf[(size_t)ROWS*DIM];
__device__ __align__(128) __nv_bfloat16 g_X2[(size_t)ROWS*K3];
__device__ __align__(128) float         g_O[(size_t)ROWS*DIM];

// ---------------- helpers ----------------
__device__ __forceinline__ uint32_t smem_u32(const void* p){
    uint32_t a;
    asm("{ .reg .u64 t; cvta.to.shared.u64 t, %1; cvt.u32.u64 %0, t; }" : "=r"(a) : "l"(p));
    return a;
}
#define SWZ128(o) ((o) ^ (((o) >> 3) & 0x70))
__device__ __forceinline__ void cpa16(uint32_t d, const void* s){
    asm volatile("cp.async.cg.shared.global [%0], [%1], 16;" :: "r"(d), "l"(s));
}
__device__ __forceinline__ void ldsm4(uint32_t* r, uint32_t addr){
    asm volatile("ldmatrix.sync.aligned.m8n8.x4.shared.b16 {%0,%1,%2,%3}, [%4];"
        : "=r"(r[0]), "=r"(r[1]), "=r"(r[2]), "=r"(r[3]) : "r"(addr));
}
__device__ __forceinline__ void mma16816(float* c, const uint32_t* a, uint32_t b0, uint32_t b1){
    asm volatile("mma.sync.aligned.m16n8k16.row.col.f32.bf16.bf16.f32 "
        "{%0,%1,%2,%3}, {%4,%5,%6,%7}, {%8,%9}, {%0,%1,%2,%3};"
        : "+f"(c[0]), "+f"(c[1]), "+f"(c[2]), "+f"(c[3])
        : "r"(a[0]), "r"(a[1]), "r"(a[2]), "r"(a[3]), "r"(b0), "r"(b1));
}
__device__ __forceinline__ void fsplit(float x, __nv_bfloat16& h, __nv_bfloat16& l){
    h = __float2bfloat16(x);
    l = __float2bfloat16(x - __bfloat162float(h));
}
__device__ __forceinline__ __nv_bfloat162 mk2(__nv_bfloat16 a, __nv_bfloat16 b){
    __nv_bfloat162 r; r.x = a; r.y = b; return r;
}
__device__ __forceinline__ float warp_sum(float v){
    #pragma unroll
    for (int o = 16; o > 0; o >>= 1) v += __shfl_xor_sync(0xFFFFFFFFu, v, o);
    return v;
}
__device__ __forceinline__ float warp_max(float v){
    #pragma unroll
    for (int o = 16; o > 0; o >>= 1) v = fmaxf(v, __shfl_xor_sync(0xFFFFFFFFu, v, o));
    return v;
}

// ================= HMMA bf16 NT GEMM (mma.sync m16n8k16) =================
// C[m,n] = alpha * sum_k A[m,k]*B[n,k] + bias ; both operands K-major bf16.
// BM=BN=128, BK=64 (128B rows, SW128 swizzle), 3-stage cp.async pipeline.
#define BM 128
#define BN 128
#define BK 64
#define STG 3
#define ATB (BM*128)            // 16384 B
#define BTB (BN*128)            // 16384 B
#define STGB (ATB+BTB)          // 32768 B
#define DSM (STG*STGB + 1024)

__device__ __forceinline__ void load_tiles(uint32_t sa, uint32_t sb,
    const __nv_bfloat16* A, const __nv_bfloat16* B, int lda, int ldb, int k0, int tid)
{
    #pragma unroll
    for (int j = 0; j < 4; j++){
        int idx = tid + 256*j; int r = idx >> 3; int kp = (idx & 7) * 16;
        cpa16(sa + SWZ128(r*128 + kp), (const char*)(A + (size_t)r*lda + k0) + kp);
    }
    #pragma unroll
    for (int j = 0; j < 4; j++){
        int idx = tid + 256*j; int r = idx >> 3; int kp = (idx & 7) * 16;
        cpa16(sb + SWZ128(r*128 + kp), (const char*)(B + (size_t)r*ldb + k0) + kp);
    }
    asm volatile("cp.async.commit_group;" ::: "memory");
}

// bias_mode: 0 none, 1 per-n, 2 per-m
__global__ void __launch_bounds__(256) gemm_bf16(
    const __nv_bfloat16* __restrict__ A, const __nv_bfloat16* __restrict__ B,
    int K2, int lda, int ldb, size_t strA, size_t strB,
    float* __restrict__ C, int ldc, size_t strC,
    float alpha, const float* __restrict__ bias, int bias_mode)
{
    extern __shared__ char dyn[];
    uint32_t tiles = (smem_u32(dyn) + 1023u) & ~1023u;
    int tid = threadIdx.x, wid = tid >> 5, lane = tid & 31;
    int wrow = wid >> 2, wcol = wid & 3;       // 2 x 4 warp grid: 64m x 32n per warp

    const __nv_bfloat16* Ab = A + blockIdx.z*strA + (size_t)blockIdx.y*BM*lda;
    const __nv_bfloat16* Bb = B + blockIdx.z*strB + (size_t)blockIdx.x*BN*ldb;
    int nch = K2 / BK;

    float c[4][4][4];
    #pragma unroll
    for (int i = 0; i < 4; i++)
        #pragma unroll
        for (int j = 0; j < 4; j++)
            #pragma unroll
            for (int r = 0; r < 4; r++) c[i][j][r] = 0.f;

    load_tiles(tiles,        tiles + ATB,        Ab, Bb, lda, ldb, 0,  tid);
    load_tiles(tiles + STGB, tiles + STGB + ATB, Ab, Bb, lda, ldb, BK, tid);

    // ldmatrix base rows (per lane)
    int aRow = wrow*64 + (lane & 15);
    int bRow = wcol*32 + (lane & 15);
    int kHi  = lane >> 4;                      // 0 or 1 -> second 8-col group

    for (int i = 0; i < nch; i++){
        if (i + 2 < nch) asm volatile("cp.async.wait_group 1;" ::: "memory");
        else             asm volatile("cp.async.wait_group 0;" ::: "memory");
        __syncthreads();
        if (i + 2 < nch){
            int slot = (i + 2) % STG;
            load_tiles(tiles + slot*STGB, tiles + slot*STGB + ATB, Ab, Bb, lda, ldb, (i+2)*BK, tid);
        }
        uint32_t sa = tiles + (i % STG)*STGB;
        uint32_t sb = sa + ATB;
        #pragma unroll
        for (int ks = 0; ks < 4; ks++){
            int kg = ks*2 + kHi;
            uint32_t a[4][4], b[2][4];
            #pragma unroll
            for (int mt = 0; mt < 4; mt++)
                ldsm4(a[mt], sa + SWZ128((aRow + mt*16)*128 + kg*16));
            #pragma unroll
            for (int bt = 0; bt < 2; bt++)
                ldsm4(b[bt], sb + SWZ128((bRow + bt*16)*128 + kg*16));
            #pragma unroll
            for (int mt = 0; mt < 4; mt++){
                mma16816(c[mt][0], a[mt], b[0][0], b[0][2]);
                mma16816(c[mt][1], a[mt], b[0][1], b[0][3]);
                mma16816(c[mt][2], a[mt], b[1][0], b[1][2]);
                mma16816(c[mt][3], a[mt], b[1][1], b[1][3]);
            }
        }
        __syncthreads();
    }

    // ---------------- epilogue ----------------
    int gmBase = blockIdx.y*BM + wrow*64 + (lane >> 2);
    int gnBase = blockIdx.x*BN + wcol*32 + (lane & 3)*2;
    float* Cz = C + blockIdx.z*strC;
    #pragma unroll
    for (int mt = 0; mt < 4; mt++){
        #pragma unroll
        for (int half = 0; half < 2; half++){
            int gm = gmBase + mt*16 + half*8;
            float rb = (bias_mode == 2) ? bias[gm] : 0.f;
            float* crow = Cz + (size_t)gm*ldc;
            #pragma unroll
            for (int nt = 0; nt < 4; nt++){
                int gn = gnBase + nt*8;
                float v0 = c[mt][nt][half*2+0] * alpha;
                float v1 = c[mt][nt][half*2+1] * alpha;
                if (bias_mode == 1){ v0 += bias[gn]; v1 += bias[gn+1]; }
                else               { v0 += rb;       v1 += rb; }
                float2 o; o.x = v0; o.y = v1;
                *(float2*)(crow + gn) = o;
            }
        }
    }
}

// ================= input LN -> split norms (both patterns) =================
__global__ void ln_in_kernel(const float* __restrict__ text, const float* __restrict__ img,
                             const float* __restrict__ gt, const float* __restrict__ bt,
                             const float* __restrict__ gi, const float* __restrict__ bi,
                             __nv_bfloat16* __restrict__ nA, __nv_bfloat16* __restrict__ nBp)
{
    int row = blockIdx.x;
    const float* src; const float* g; const float* b;
    if (row < 2*SLEN){ src = text + (size_t)row*DIM;            g = gt; b = bt; }
    else             { src = img  + (size_t)(row - 2*SLEN)*DIM; g = gi; b = bi; }
    int t = threadIdx.x;
    float4 v = ((const float4*)src)[t];
    float s  = v.x + v.y + v.z + v.w;
    float ss = v.x*v.x + v.y*v.y + v.z*v.z + v.w*v.w;
    __shared__ float red[8];
    s = warp_sum(s); ss = warp_sum(ss);
    int w = t >> 5, l = t & 31;
    if (l == 0){ red[w] = s; red[4+w] = ss; }
    __syncthreads();
    float st = red[0]+red[1]+red[2]+red[3], sst = red[4]+red[5]+red[6]+red[7];
    float mu = st * (1.0f/DIM), var = sst * (1.0f/DIM) - mu*mu;
    float r = rsqrtf(var + 1e-5f);
    float4 gv = ((const float4*)g)[t], bv = ((const float4*)b)[t];
    float o0 = (v.x-mu)*r*gv.x + bv.x, o1 = (v.y-mu)*r*gv.y + bv.y;
    float o2 = (v.z-mu)*r*gv.z + bv.z, o3 = (v.w-mu)*r*gv.w + bv.w;
    __nv_bfloat16 h0,l0,h1,l1,h2,l2,h3,l3;
    fsplit(o0,h0,l0); fsplit(o1,h1,l1); fsplit(o2,h2,l2); fsplit(o3,h3,l3);
    __nv_bfloat162 hp0 = mk2(h0,h1), hp1 = mk2(h2,h3), lp0 = mk2(l0,l1), lp1 = mk2(l2,l3);
    size_t base = (size_t)row*K3 + t*4;
    *(__nv_bfloat162*)(nA + base)           = hp0; *(__nv_bfloat162*)(nA + base + 2)          = hp1;
    *(__nv_bfloat162*)(nA + base + DIM)     = hp0; *(__nv_bfloat162*)(nA + base + DIM + 2)    = hp1;
    *(__nv_bfloat162*)(nA + base + 2*DIM)   = lp0; *(__nv_bfloat162*)(nA + base + 2*DIM + 2)  = lp1;
    *(__nv_bfloat162*)(nBp + base)          = hp0; *(__nv_bfloat162*)(nBp + base + 2)         = hp1;
    *(__nv_bfloat162*)(nBp + base + DIM)    = lp0; *(__nv_bfloat162*)(nBp + base + DIM + 2)   = lp1;
    *(__nv_bfloat162*)(nBp + base + 2*DIM)  = hp0; *(__nv_bfloat162*)(nBp + base + 2*DIM + 2) = hp1;
}

// ================= generic fp32 -> split-bf16 (tripled-K) =================
// pattern 0 (A operand): hi,hi,lo ; pattern 1 (B operand): hi,lo,hi
__global__ void split_kernel(const float* __restrict__ in, __nv_bfloat16* __restrict__ out,
                             int C, int bpat)
{
    size_t row = blockIdx.x;
    const float* src = in + row * (size_t)C;
    __nv_bfloat16* dst = out + row * (size_t)(3*C);
    for (int c = threadIdx.x * 2; c < C; c += blockDim.x * 2){
        float2 v = *(const float2*)(src + c);
        __nv_bfloat16 h0,l0,h1,l1; fsplit(v.x,h0,l0); fsplit(v.y,h1,l1);
        __nv_bfloat162 hp = mk2(h0,h1), lp = mk2(l0,l1);
        *(__nv_bfloat162*)(dst + c)       = hp;
        *(__nv_bfloat162*)(dst + C + c)   = bpat ? lp : hp;
        *(__nv_bfloat162*)(dst + 2*C + c) = bpat ? hp : lp;
    }
}

// V^T fp32 [512 x 16384] -> per-batch B-pattern bf16 [4][512][12288]
__global__ void split_vt_kernel(const float* __restrict__ Vt, __nv_bfloat16* __restrict__ out)
{
    int d = blockIdx.x, b = blockIdx.y;
    const float* src = Vt + (size_t)d * ROWS + (size_t)b * SLEN;
    __nv_bfloat16* dst = out + ((size_t)b * DIM + d) * KP3;
    for (int s = threadIdx.x * 2; s < SLEN; s += blockDim.x * 2){
        float2 v = *(const float2*)(src + s);
        __nv_bfloat16 h0,l0,h1,l1; fsplit(v.x,h0,l0); fsplit(v.y,h1,l1);
        __nv_bfloat162 hp = mk2(h0,h1), lp = mk2(l0,l1);
        *(__nv_bfloat162*)(dst + s)          = hp;
        *(__nv_bfloat162*)(dst + SLEN + s)   = lp;
        *(__nv_bfloat162*)(dst + 2*SLEN + s) = hp;
    }
}

// ================= softmax fused with probs split (A-pattern tripled-K) ========
// Reads fp32 scores, writes tripled-K bf16 probs directly: [hi | hi | lo].
__global__ void softmax_split_kernel(const float* __restrict__ Sc,
                                     __nv_bfloat16* __restrict__ P2)
{
    size_t row = blockIdx.x;
    const float4* p = (const float4*)(Sc + row * (size_t)SLEN);
    __nv_bfloat16* dst = P2 + row * (size_t)KP3;
    int t = threadIdx.x;
    float4 v[4];
    #pragma unroll
    for (int i = 0; i < 4; i++) v[i] = p[t + i*256];
    float m = -1e30f;
    #pragma unroll
    for (int i = 0; i < 4; i++)
        m = fmaxf(m, fmaxf(fmaxf(v[i].x, v[i].y), fmaxf(v[i].z, v[i].w)));
    __shared__ float red[8];
    m = warp_max(m);
    int w = t >> 5, l = t & 31;
    if (l == 0) red[w] = m;
    __syncthreads();
    float bm = red[0];
    #pragma unroll
    for (int i = 1; i < 8; i++) bm = fmaxf(bm, red[i]);
    float sum = 0.0f;
    #pragma unroll
    for (int i = 0; i < 4; i++){
        v[i].x = __expf(v[i].x - bm); v[i].y = __expf(v[i].y - bm);
        v[i].z = __expf(v[i].z - bm); v[i].w = __expf(v[i].w - bm);
        sum += v[i].x + v[i].y + v[i].z + v[i].w;
    }
    sum = warp_sum(sum);
    __syncthreads();
    if (l == 0) red[w] = sum;
    __syncthreads();
    float bs = red[0]+red[1]+red[2]+red[3]+red[4]+red[5]+red[6]+red[7];
    float inv = 1.0f / bs;
    #pragma unroll
    for (int i = 0; i < 4; i++){
        float p0 = v[i].x * inv, p1 = v[i].y * inv, p2 = v[i].z * inv, p3 = v[i].w * inv;
        __nv_bfloat16 h0,l0b,h1,l1b,h2,l2b,h3,l3b;
        fsplit(p0,h0,l0b); fsplit(p1,h1,l1b); fsplit(p2,h2,l2b); fsplit(p3,h3,l3b);
        __nv_bfloat162 hpa = mk2(h0,h1), hpb = mk2(h2,h3);
        __nv_bfloat162 lpa = mk2(l0b,l1b), lpb = mk2(l2b,l3b);
        int c = (t + i*256) * 4;
        *(__nv_bfloat162*)(dst + c)              = hpa; *(__nv_bfloat162*)(dst + c + 2)            = hpb;
        *(__nv_bfloat162*)(dst + SLEN + c)       = hpa; *(__nv_bfloat162*)(dst + SLEN + c + 2)     = hpb;
        *(__nv_bfloat162*)(dst + 2*SLEN + c)     = lpa; *(__nv_bfloat162*)(dst + 2*SLEN + c + 2)   = lpb;
    }
}

// ================= output double LayerNorm =================
__global__ void ln_out_kernel(const float* __restrict__ X,
                              const float* __restrict__ gt, const float* __restrict__ bt,
                              const float* __restrict__ gi, const float* __restrict__ bi,
                              float* __restrict__ out)
{
    int row = blockIdx.x;
    int t = threadIdx.x;
    float4 v = ((const float4*)(X + (size_t)row*DIM))[t];
    float s  = v.x + v.y + v.z + v.w;
    float ss = v.x*v.x + v.y*v.y + v.z*v.z + v.w*v.w;
    __shared__ float red[8];
    s = warp_sum(s); ss = warp_sum(ss);
    int w = t >> 5, l = t & 31;
    if (l == 0){ red[w] = s; red[4+w] = ss; }
    __syncthreads();
    float st  = red[0]+red[1]+red[2]+red[3];
    float sst = red[4]+red[5]+red[6]+red[7];
    float mu  = st * (1.0f/DIM);
    float var = sst * (1.0f/DIM) - mu*mu;
    float r   = rsqrtf(var + 1e-5f);
    float nx = (v.x-mu)*r, ny = (v.y-mu)*r, nz = (v.z-mu)*r, nw = (v.w-mu)*r;
    float4 g1 = ((const float4*)gt)[t]; float4 b1 = ((const float4*)bt)[t];
    float4 o1; o1.x = nx*g1.x + b1.x; o1.y = ny*g1.y + b1.y;
               o1.z = nz*g1.z + b1.z; o1.w = nw*g1.w + b1.w;
    ((float4*)(out + (size_t)row*DIM))[t] = o1;
    float4 g2 = ((const float4*)gi)[t]; float4 b2 = ((const float4*)bi)[t];
    float4 o2; o2.x = nx*g2.x + b2.x; o2.y = ny*g2.y + b2.y;
               o2.z = nz*g2.z + b2.z; o2.w = nw*g2.w + b2.w;
    ((float4*)(out + (size_t)(ROWS + row)*DIM))[t] = o2;
}

// ================= launch =================
extern "C" void kernel_launch(void* const* d_in, const int* in_sizes, int n_in,
                              void* d_out, int out_size)
{
    const float* text   = (const float*)d_in[0];
    const float* img    = (const float*)d_in[1];
    const float* ln_t_g = (const float*)d_in[2];
    const float* ln_t_b = (const float*)d_in[3];
    const float* ln_i_g = (const float*)d_in[4];
    const float* ln_i_b = (const float*)d_in[5];
    const float* Wq  = (const float*)d_in[6];  const float* bq  = (const float*)d_in[7];
    const float* Wkt = (const float*)d_in[8];  const float* bkt = (const float*)d_in[9];
    const float* Wvt = (const float*)d_in[10]; const float* bvt = (const float*)d_in[11];
    const float* Wki = (const float*)d_in[12]; const float* bki = (const float*)d_in[13];
    const float* Wvi = (const float*)d_in[14]; const float* bvi = (const float*)d_in[15];
    const float* Wo  = (const float*)d_in[16]; const float* bo  = (const float*)d_in[17];
    float* out = (float*)d_out;

    __nv_bfloat16 *nA, *nBp, *W2, *Q2, *K2p, *Vt2, *P2, *X2;
    float *Qf, *Kf, *Vtf, *Sc, *Xf, *Of;
    cudaGetSymbolAddress((void**)&nA,  g_nA);
    cudaGetSymbolAddress((void**)&nBp, g_nB);
    cudaGetSymbolAddress((void**)&W2,  g_W2);
    cudaGetSymbolAddress((void**)&Qf,  g_Qf);
    cudaGetSymbolAddress((void**)&Q2,  g_Q2);
    cudaGetSymbolAddress((void**)&Kf,  g_Kf);
    cudaGetSymbolAddress((void**)&K2p, g_K2);
    cudaGetSymbolAddress((void**)&Vtf, g_Vtf);
    cudaGetSymbolAddress((void**)&Vt2, g_Vt2);
    cudaGetSymbolAddress((void**)&Sc,  g_Sc);
    cudaGetSymbolAddress((void**)&P2,  g_P2);
    cudaGetSymbolAddress((void**)&Xf,  g_Xf);
    cudaGetSymbolAddress((void**)&X2,  g_X2);
    cudaGetSymbolAddress((void**)&Of,  g_O);

    cudaFuncSetAttribute(gemm_bf16, cudaFuncAttributeMaxDynamicSharedMemorySize, DSM);

    const size_t WSTR = (size_t)DIM * K3;
    const float scale = 0.044194173824159216f;    // 512^-0.5

    // 1) input LN -> split norms (both operand patterns)
    ln_in_kernel<<<ROWS, 128>>>(text, img, ln_t_g, ln_t_b, ln_i_g, ln_i_b, nA, nBp);

    // 2) split weights: Wq,Wkt,Wki,Wo B-pattern; Wvt,Wvi A-pattern
    split_kernel<<<DIM, 256>>>(Wq,  W2 + 0*WSTR, DIM, 1);
    split_kernel<<<DIM, 256>>>(Wkt, W2 + 1*WSTR, DIM, 1);
    split_kernel<<<DIM, 256>>>(Wki, W2 + 2*WSTR, DIM, 1);
    split_kernel<<<DIM, 256>>>(Wvt, W2 + 3*WSTR, DIM, 0);
    split_kernel<<<DIM, 256>>>(Wvi, W2 + 4*WSTR, DIM, 0);
    split_kernel<<<DIM, 256>>>(Wo,  W2 + 5*WSTR, DIM, 1);

    // 3) Q = norms @ Wq^T + bq   [16384 x 512]
    gemm_bf16<<<dim3(DIM/BN, ROWS/BM, 1), 256, DSM>>>(
        nA, W2 + 0*WSTR, K3, K3, K3, 0, 0, Qf, DIM, 0, 1.0f, bq, 1);
    // 4) K: text rows with Wkt, img rows with Wki
    gemm_bf16<<<dim3(DIM/BN, (ROWS/2)/BM, 1), 256, DSM>>>(
        nA, W2 + 1*WSTR, K3, K3, K3, 0, 0, Kf, DIM, 0, 1.0f, bkt, 1);
    gemm_bf16<<<dim3(DIM/BN, (ROWS/2)/BM, 1), 256, DSM>>>(
        nA + (size_t)(ROWS/2)*K3, W2 + 2*WSTR, K3, K3, K3, 0, 0,
        Kf + (size_t)(ROWS/2)*DIM, DIM, 0, 1.0f, bki, 1);
    // 5) V^T = Wv @ norms^T + bv (per-row bias)  [512 x 16384]
    gemm_bf16<<<dim3((ROWS/2)/BN, DIM/BM, 1), 256, DSM>>>(
        W2 + 3*WSTR, nBp, K3, K3, K3, 0, 0, Vtf, ROWS, 0, 1.0f, bvt, 2);
    gemm_bf16<<<dim3((ROWS/2)/BN, DIM/BM, 1), 256, DSM>>>(
        W2 + 4*WSTR, nBp + (size_t)(ROWS/2)*K3, K3, K3, K3, 0, 0,
        Vtf + ROWS/2, ROWS, 0, 1.0f, bvi, 2);

    // 6) split Q (A-pattern), K (B-pattern), V^T (B-pattern per batch)
    split_kernel<<<ROWS, 256>>>(Qf, Q2, DIM, 0);
    split_kernel<<<ROWS, 256>>>(Kf, K2p, DIM, 1);
    split_vt_kernel<<<dim3(DIM, NB), 256>>>(Vtf, Vt2);

    // 7) scores = scale * Q @ K^T   [4][4096 x 4096]
    gemm_bf16<<<dim3(SLEN/BN, SLEN/BM, NB), 256, DSM>>>(
        Q2, K2p, K3, K3, K3, (size_t)SLEN*K3, (size_t)SLEN*K3,
        Sc, SLEN, (size_t)SLEN*SLEN, scale, nullptr, 0);

    // 8) softmax + probs split fused (writes tripled-K bf16 directly)
    softmax_split_kernel<<<ROWS, 256>>>(Sc, P2);

    // 9) x = P @ V   [4][4096 x 512]
    gemm_bf16<<<dim3(DIM/BN, SLEN/BM, NB), 256, DSM>>>(
        P2, Vt2, KP3, KP3, KP3, (size_t)SLEN*KP3, (size_t)DIM*KP3,
        Xf, DIM, (size_t)SLEN*DIM, 1.0f, nullptr, 0);

    // 10) split x, out-proj
    split_kernel<<<ROWS, 256>>>(Xf, X2, DIM, 0);
    gemm_bf16<<<dim3(DIM/BN, ROWS/BM, 1), 256, DSM>>>(
        X2, W2 + 5*WSTR, K3, K3, K3, 0, 0, Of, DIM, 0, 1.0f, bo, 1);

    // 11) final double LayerNorm
    ln_out_kernel<<<ROWS, 128>>>(Of, ln_t_g, ln_t_b, ln_i_g, ln_i_b, out);
}